// round 15
// baseline (speedup 1.0000x reference)
#include <cuda_runtime.h>
#include <cstdint>

#define NB    148
#define NT    1024
#define NWARP (NT / 32)
#define NWT   (NB * NWARP)          // 4736 warps
#define NPAD  8192
#define PREC  (NPAD / 2)            // 4096 records
#define RPAN  (NPAD / 128)          // 64 panels
#define WTOT  (RPAN * (PREC - 32 * (RPAN - 1)))   // 133120 work units

#define PACKF2(r, lo, hi)   asm("mov.b64 %0, {%1, %2};" : "=l"(r) : "f"(lo), "f"(hi))
#define UNPACKF2(lo, hi, x) asm("mov.b64 {%0, %1}, %2;" : "=f"(lo), "=f"(hi) : "l"(x))
#define FMAF2(r, a, b, c)   asm("fma.rn.f32x2 %0, %1, %2, %3;" : "=l"(r) : "l"(a), "l"(b), "l"(c))

// dynamic smem: 64KB; record r (cols 2r,2r+1) 16B: { -p0, -p1, t0, t1 } (masked)
#define SMEM_BYTES 65536

__device__ unsigned long long g_acc  = 0ULL;   // fixed-point (2^16) two's complement
__device__ float              g_sums[5];       // sp, st, spt, src, cnt (block 0 only)
__device__ unsigned int       g_done = 0;

__global__ __launch_bounds__(NT, 1)
void cindex_kernel(const float* __restrict__ pred,
                   const float* __restrict__ gt,
                   const int* __restrict__ ft_idx,
                   const int* __restrict__ fm_idx,
                   float* __restrict__ out, int n)
{
    extern __shared__ unsigned char smem_raw[];
    float4*           r1q4 = (float4*)smem_raw;
    const ulonglong2* r1v  = (const ulonglong2*)smem_raw;
    const float4*     r1q  = (const float4*)smem_raw;
    __shared__ float red[6][NWARP];

    const int tid   = threadIdx.x;
    const int lane  = tid & 31;
    const int wid   = tid >> 5;
    const int fmi   = fm_idx[0];
    const int fti   = ft_idx[0];
    const bool blk0 = (blockIdx.x == 0);

    // ---- Phase A: masked staging (no compaction), ONE barrier ----
    float sp = 0.f, st = 0.f, spt = 0.f, src = 0.f, cntf = 0.f;
    #pragma unroll
    for (int q = 0; q < PREC / NT; ++q) {
        const int r = q * NT + tid;
        float pa = 0.f, pb = 0.f, ta = 0.f, tb = 0.f;
        if (2 * r + 1 < n) {
            float4 g  = ((const float4*)gt)[r];
            float2 pp = ((const float2*)pred)[r];
            float wa = fmi ? g.y : g.x, va = fti ? g.y : g.x;
            float wb = fmi ? g.w : g.z, vb = fti ? g.w : g.z;
            if (wa == 1.0f) { pa = pp.x; ta = va; }
            if (wb == 1.0f) { pb = pp.y; tb = vb; }
        } else if (2 * r < n) {
            float2 g = ((const float2*)gt)[2 * r];
            float wa = fmi ? g.y : g.x, va = fti ? g.y : g.x;
            if (wa == 1.0f) { pa = pred[2 * r]; ta = va; }
        }
        if (blk0) {                      // only block 0 owns the elementwise sums
            float ca = pa * ta, cb = pb * tb;
            sp  += pa + pb;
            st  += ta + tb;
            spt += ca + cb;
            src += fmaxf(ca, 0.f) + fmaxf(cb, 0.f);
            cntf += (pa != 0.f || ta != 0.f ? 1.f : 0.f)
                  + (pb != 0.f || tb != 0.f ? 1.f : 0.f);
        }
        r1q4[r] = make_float4(-pa, -pb, ta, tb);
    }
    __syncthreads();

    // ---- Phase B: static warp-panel triangle; 4xFFMA2 + packed-abs (alu) ----
    float v = 0.f;
    uint64_t one2, mone2, zero2;
    PACKF2(one2, 1.0f, 1.0f);
    PACKF2(mone2, -1.0f, -1.0f);
    PACKF2(zero2, 0.0f, 0.0f);
    {
        const unsigned uw = (unsigned)(blockIdx.x * NWARP + wid);
        const unsigned w0 = (unsigned)(uw * (unsigned)WTOT) / (unsigned)NWT;
        const unsigned w1 = (unsigned)((uw + 1) * (unsigned)WTOT) / (unsigned)NWT;

        int p;
        {
            const float A = (float)(PREC + 32);
            float disc = fmaxf(A * A - 128.0f * (float)w0, 0.0f);
            p = (int)((A - sqrtf(disc)) * (1.0f / 64.0f));
            if (p < 0) p = 0;
            if (p > RPAN - 1) p = RPAN - 1;
            while (p + 1 <= RPAN - 1 &&
                   (unsigned)(p + 1) * (PREC - 32 * p) <= w0) ++p;
            while (p > 0 && (unsigned)p * (PREC - 32 * (p - 1)) > w0) --p;
        }

        unsigned w = w0;
        while (w < w1) {
            const unsigned cs   = (unsigned)p * (PREC - 32 * (p - 1));
            const unsigned pend = cs + (PREC - 64 * p);

            const int rbase = 64 * p + 2 * lane;     // lane's 4 rows (2 records)
            float4 a = r1q[rbase];
            float4 b = r1q[rbase + 1];
            uint64_t pi2[4], ti2[4];
            PACKF2(pi2[0], -a.x, -a.x); PACKF2(ti2[0], a.z, a.z);
            PACKF2(pi2[1], -a.y, -a.y); PACKF2(ti2[1], a.w, a.w);
            PACKF2(pi2[2], -b.x, -b.x); PACKF2(ti2[2], b.z, b.z);
            PACKF2(pi2[3], -b.y, -b.y); PACKF2(ti2[3], b.w, b.w);

            const unsigned dlim = min(pend, cs + 64u);
            #pragma unroll
            for (int seg = 0; seg < 2; ++seg) {
                const unsigned send = min(w1, seg == 0 ? dlim : pend);
                if (w < send) {
                    int k = 64 * p + (int)(w - cs);
                    const int kn = k + (int)(send - w);
                    uint64_t acc2[4] = {0, 0, 0, 0};
                    #pragma unroll 4
                    for (; k < kn; ++k) {
                        ulonglong2 va = r1v[k];          // broadcast LDS.128
                        #pragma unroll
                        for (int r = 0; r < 4; ++r) {
                            uint64_t dp2, dt2, x2, ax;
                            FMAF2(dp2, pi2[r], one2, va.x);   // pi - pj   (fma)
                            FMAF2(dt2, va.y, mone2, ti2[r]);  // ti - tj   (fma)
                            FMAF2(x2, dp2, dt2, zero2);       // dp*dt     (fma)
                            ax = x2 & 0x7fffffff7fffffffULL;  // |.|  (alu: 2 LOP3)
                            FMAF2(acc2[r], ax, one2, acc2[r]);// acc += |x| (fma)
                        }
                    }
                    const float wt = (seg == 0) ? 0.5f : 1.0f;  // diag halved
                    #pragma unroll
                    for (int r = 0; r < 4; ++r) {
                        float lo, hi;
                        UNPACKF2(lo, hi, acc2[r]);
                        v += wt * (lo + hi);
                    }
                    w = send;
                }
            }
            ++p;
        }
    }

    // ---- Phase C: slim tail. All blocks reduce v; block 0 also reduces sums ----
    #pragma unroll
    for (int o = 16; o > 0; o >>= 1)
        v += __shfl_down_sync(0xffffffffu, v, o);
    if (lane == 0) red[0][wid] = v;
    if (blk0) {
        float s5[5] = {sp, st, spt, src, cntf};
        #pragma unroll
        for (int j = 0; j < 5; ++j) {
            #pragma unroll
            for (int o = 16; o > 0; o >>= 1)
                s5[j] += __shfl_down_sync(0xffffffffu, s5[j], o);
            if (lane == 0) red[j + 1][wid] = s5[j];
        }
    }
    __syncthreads();
    if (wid == 0) {
        float tv = red[0][lane];
        #pragma unroll
        for (int o = 16; o > 0; o >>= 1)
            tv += __shfl_down_sync(0xffffffffu, tv, o);

        if (blk0) {                          // block 0 publishes the shared sums
            float tj = 0.f;
            if (lane == 0) {
                float a1 = red[1][0], a2 = red[2][0];  // placeholder; real below
                (void)a1; (void)a2;
            }
            #pragma unroll
            for (int j = 0; j < 5; ++j) {
                tj = red[j + 1][lane];
                #pragma unroll
                for (int o = 16; o > 0; o >>= 1)
                    tj += __shfl_down_sync(0xffffffffu, tj, o);
                if (lane == 0) g_sums[j] = tj;
            }
        }

        unsigned rank = 0;
        if (lane == 0) {
            long long q = llrint((double)tv * 65536.0);
            atomicAdd(&g_acc, (unsigned long long)q);
            __threadfence();
            rank = atomicAdd(&g_done, 1u);
        }
        rank = __shfl_sync(0xffffffffu, rank, 0);

        if (rank == (unsigned)(gridDim.x - 1) && lane == 0) {   // last block
            __threadfence();                                     // acquire
            double absum = (double)(long long)g_acc / 65536.0;   // Σ|z'|
            double tsp  = (double)__ldcg(&g_sums[0]);
            double tst  = (double)__ldcg(&g_sums[1]);
            double tspt = (double)__ldcg(&g_sums[2]);
            double tsrc = (double)__ldcg(&g_sums[3]);
            double m    = (double)__ldcg(&g_sums[4]);
            double Sz = (double)NPAD * tspt - tsp * tst;
            double Rp = 0.5 * (Sz + absum);
            double target = Rp - ((double)NPAD - m) * tsrc;
            float res = 0.0f;
            if (m > 1.5)
                res = (float)(target / (50.0 * m * (m - 1.0)));
            out[0] = res;
            g_acc = 0ULL;                    // self-clean for next call
            g_done = 0u;
        }
    }
}

extern "C" void kernel_launch(void* const* d_in, const int* in_sizes, int n_in,
                              void* d_out, int out_size) {
    const float* pred = (const float*)d_in[0];
    const float* gt   = (const float*)d_in[1];
    const int* ft     = (const int*)d_in[2];
    const int* fm     = (const int*)d_in[3];
    float* out        = (float*)d_out;
    const int n = in_sizes[0];

    cudaFuncSetAttribute(cindex_kernel,
                         cudaFuncAttributeMaxDynamicSharedMemorySize, SMEM_BYTES);
    cindex_kernel<<<NB, NT, SMEM_BYTES>>>(pred, gt, ft, fm, out, n);
}

// round 16
// speedup vs baseline: 1.1223x; 1.1223x over previous
#include <cuda_runtime.h>
#include <cstdint>

#define NB    148
#define NT    1024
#define NWARP (NT / 32)
#define NWT   (NB * NWARP)      // 4736 warps
#define MAXQ  8                 // ceil(8192 / NT)

#define PACKF2(r, lo, hi)   asm("mov.b64 %0, {%1, %2};" : "=l"(r) : "f"(lo), "f"(hi))
#define UNPACKF2(lo, hi, x) asm("mov.b64 {%0, %1}, %2;" : "=f"(lo), "=f"(hi) : "l"(x))
// real packed op on sm_100a: fma.rn.f32x2 -> FFMA2
#define FMAF2(r, a, b, c)   asm("fma.rn.f32x2 %0, %1, %2, %3;" : "=l"(r) : "l"(a), "l"(b), "l"(c))

// dynamic smem: 64KB; record (2 cols) 16B: { -p0, -p1, t0, t1 }
#define SMEM_BYTES 65536

__device__ unsigned long long g_acc  = 0ULL;  // fixed-point (2^16), two's complement
__device__ unsigned int       g_done = 0;

__global__ __launch_bounds__(NT, 1)
void cindex_kernel(const float* __restrict__ pred,
                   const float* __restrict__ gt,
                   const int* __restrict__ ft_idx,
                   const int* __restrict__ fm_idx,
                   float* __restrict__ out, int n)
{
    extern __shared__ unsigned char smem_raw[];
    float*            r1f = (float*)smem_raw;
    const ulonglong2* r1v = (const ulonglong2*)smem_raw;
    const float4*     r1q = (const float4*)smem_raw;
    __shared__ int   iscn[NWARP];
    __shared__ int   s_m;
    __shared__ float redv[NWARP], redp[NWARP], redt[NWARP], redpt[NWARP];

    const int tid  = threadIdx.x;
    const int lane = tid & 31;
    const int wid  = tid >> 5;
    const int fmi  = fm_idx[0];
    const int fti  = ft_idx[0];

    // ---- Phase A1: coalesced load + flag count + flagged sums ----
    float rp[MAXQ], rt[MAXQ];
    unsigned flags = 0;
    int cnt = 0;
    float sp = 0.0f, st = 0.0f, spt = 0.0f;
    #pragma unroll
    for (int q = 0; q < MAXQ; ++q) {
        const int e = q * NT + tid;
        if (e < n) {
            float2 gg = ((const float2*)gt)[e];
            float w  = fmi ? gg.y : gg.x;
            float tv = fti ? gg.y : gg.x;
            float pv = pred[e];
            rp[q] = pv; rt[q] = tv;
            if (w == 1.0f) {
                flags |= 1u << q; cnt++;
                sp += pv; st += tv; spt += pv * tv;
            }
        }
    }

    // ---- Phase A2: deterministic block scan of counts ----
    int incl = cnt;
    #pragma unroll
    for (int o = 1; o < 32; o <<= 1) {
        int v = __shfl_up_sync(0xffffffffu, incl, o);
        if (lane >= o) incl += v;
    }
    if (lane == 31) iscn[wid] = incl;
    __syncthreads();
    if (wid == 0) {
        int v = (lane < NWARP) ? iscn[lane] : 0;
        #pragma unroll
        for (int o = 1; o < 32; o <<= 1) {
            int u2 = __shfl_up_sync(0xffffffffu, v, o);
            if (lane >= o) v += u2;
        }
        if (lane < NWARP) iscn[lane] = v;
        if (lane == NWARP - 1) s_m = v;
    }
    __syncthreads();
    const int m = s_m;
    int idx = (wid ? iscn[wid - 1] : 0) + (incl - cnt);

    // ---- Phase A3: deterministic compacted scatter: { -p, t } ----
    #pragma unroll
    for (int q = 0; q < MAXQ; ++q) {
        if (flags & (1u << q)) {
            const int rec = idx >> 1, o = idx & 1;
            r1f[rec * 4 +     o] = -rp[q];
            r1f[rec * 4 + 2 + o] =  rt[q];
            idx++;
        }
    }
    if (tid == 0 && (m & 1)) {          // zero-pad odd column
        const int rec = m >> 1;
        r1f[rec * 4 + 1] = 0.0f;
        r1f[rec * 4 + 3] = 0.0f;
    }
    __syncthreads();

    // ---- Phase B: warp-panel triangle, 3xFFMA2 + 2xFADD.|| per 2 pairs ----
    float v = 0.0f;
    uint64_t one2, mone2, zero2;
    PACKF2(one2, 1.0f, 1.0f);
    PACKF2(mone2, -1.0f, -1.0f);
    PACKF2(zero2, 0.0f, 0.0f);
    if (m > 1) {
        const int P  = (m + 1) >> 1;
        const int RP = (m + 127) >> 7;
        const unsigned W = (unsigned)(RP * (P - 32 * (RP - 1)));
        const unsigned uw = (unsigned)(blockIdx.x * NWARP + wid);
        const unsigned w0 = (unsigned)((unsigned long long)uw * W / NWT);
        const unsigned w1 = (unsigned)((unsigned long long)(uw + 1) * W / NWT);

        if (w0 < w1) {
            int p;
            {
                float A = (float)(P + 32);
                float disc = fmaxf(A * A - 128.0f * (float)w0, 0.0f);
                p = (int)((A - sqrtf(disc)) * (1.0f / 64.0f));
                if (p < 0) p = 0;
                if (p > RP - 1) p = RP - 1;
                while (p + 1 <= RP - 1 && (p + 1) * (P - 32 * p) <= (int)w0) ++p;
                while (p > 0 && p * (P - 32 * (p - 1)) > (int)w0) --p;
            }

            unsigned w = w0;
            while (w < w1) {
                const int cs   = p * (P - 32 * (p - 1));     // Cpre(p)
                const int pend = cs + (P - 64 * p);

                // panel rows for this lane: rows 128p + 4*lane .. +3
                const int rbase = 64 * p + 2 * lane;
                float4 a = r1q[rbase];          // {-p0,-p1, t0,t1}
                float4 b = r1q[rbase + 1];      // rows +2,+3
                uint64_t pi2[4], ti2[4];
                PACKF2(pi2[0], -a.x, -a.x); PACKF2(ti2[0], a.z, a.z);
                PACKF2(pi2[1], -a.y, -a.y); PACKF2(ti2[1], a.w, a.w);
                PACKF2(pi2[2], -b.x, -b.x); PACKF2(ti2[2], b.z, b.z);
                PACKF2(pi2[3], -b.y, -b.y); PACKF2(ti2[3], b.w, b.w);
                const int row0 = 128 * p + 4 * lane;

                const unsigned dlim = (unsigned)min(pend, cs + 64);
                #pragma unroll
                for (int seg = 0; seg < 2; ++seg) {
                    const unsigned send = min(w1, seg == 0 ? dlim : (unsigned)pend);
                    if (w < send) {
                        int k  = 64 * p + (int)(w - (unsigned)cs);
                        const int kn = k + (int)(send - w);
                        float aL[4] = {0, 0, 0, 0}, aH[4] = {0, 0, 0, 0};
                        #pragma unroll 2
                        for (; k < kn; ++k) {
                            ulonglong2 va = r1v[k];      // {npj2 | tj2}, broadcast
                            #pragma unroll
                            for (int r = 0; r < 4; ++r) {
                                uint64_t dp2, dt2, x2;
                                FMAF2(dp2, pi2[r], one2, va.x);   // pi - pj
                                FMAF2(dt2, va.y, mone2, ti2[r]);  // ti - tj
                                FMAF2(x2, dp2, dt2, zero2);       // dp*dt
                                float xl, xh;
                                UNPACKF2(xl, xh, x2);
                                aL[r] += fabsf(xl);
                                aH[r] += fabsf(xh);
                            }
                        }
                        const float wt = (seg == 0) ? 0.5f : 1.0f;   // diag halved
                        #pragma unroll
                        for (int r = 0; r < 4; ++r)
                            if (row0 + r < m) v += wt * (aL[r] + aH[r]);
                        w = send;
                    }
                }
                ++p;
            }
        }

        // pad column added |p_i * t_i| per row (wt 1/2 in last panel): subtract
        if (m & 1) {
            const int i = blockIdx.x * NT + tid;
            if (i < m) {
                float npi = r1f[(i >> 1) * 4 +     (i & 1)];
                float ti  = r1f[(i >> 1) * 4 + 2 + (i & 1)];
                float wi = (i >= 128 * ((m + 127) >> 7) - 128) ? 0.5f : 1.0f;
                v -= wi * fabsf(npi * ti);
            }
        }
    }

    // ---- Phase C: block reduce (v, sp, st, spt) -> fixed-point global ----
    #pragma unroll
    for (int o = 16; o > 0; o >>= 1) {
        v   += __shfl_down_sync(0xffffffffu, v, o);
        sp  += __shfl_down_sync(0xffffffffu, sp, o);
        st  += __shfl_down_sync(0xffffffffu, st, o);
        spt += __shfl_down_sync(0xffffffffu, spt, o);
    }
    if (lane == 0) { redv[wid] = v; redp[wid] = sp; redt[wid] = st; redpt[wid] = spt; }
    __syncthreads();
    if (wid == 0) {
        float tv = (lane < NWARP) ? redv[lane]  : 0.0f;
        float tp = (lane < NWARP) ? redp[lane]  : 0.0f;
        float tt = (lane < NWARP) ? redt[lane]  : 0.0f;
        float tq = (lane < NWARP) ? redpt[lane] : 0.0f;
        #pragma unroll
        for (int o = 16; o > 0; o >>= 1) {
            tv += __shfl_down_sync(0xffffffffu, tv, o);
            tp += __shfl_down_sync(0xffffffffu, tp, o);
            tt += __shfl_down_sync(0xffffffffu, tt, o);
            tq += __shfl_down_sync(0xffffffffu, tq, o);
        }
        if (lane == 0) {
            long long q = llrint((double)tv * 65536.0);
            atomicAdd(&g_acc, (unsigned long long)q);
            __threadfence();
            unsigned r = atomicAdd(&g_done, 1u);
            if (r == (unsigned)(gridDim.x - 1)) {
                long long total = (long long)g_acc;
                double absum = (double)total / 65536.0;   // Σ|z| unordered
                double Sx = (double)m * (double)tq - (double)tp * (double)tt;
                double relu_sum = 0.5 * (Sx + absum);     // Σ relu(z)
                float res = 0.0f;
                if (m > 1)
                    res = (float)(relu_sum / (50.0 * (double)m * ((double)m - 1.0)));
                out[0] = res;
                g_acc = 0ULL;
                g_done = 0u;
            }
        }
    }
}

extern "C" void kernel_launch(void* const* d_in, const int* in_sizes, int n_in,
                              void* d_out, int out_size) {
    const float* pred = (const float*)d_in[0];
    const float* gt   = (const float*)d_in[1];
    const int* ft     = (const int*)d_in[2];
    const int* fm     = (const int*)d_in[3];
    float* out        = (float*)d_out;
    const int n = in_sizes[0];

    cudaFuncSetAttribute(cindex_kernel,
                         cudaFuncAttributeMaxDynamicSharedMemorySize, SMEM_BYTES);
    cindex_kernel<<<NB, NT, SMEM_BYTES>>>(pred, gt, ft, fm, out, n);
}